// round 6
// baseline (speedup 1.0000x reference)
#include <cuda_runtime.h>
#include <cuda_fp16.h>

#define N_NODES 100000
#define N_EDGES 1250000
#define D 64
#define NB 98          // scan blocks: ceil(N/1024)

// ---------------- scratch (static __device__ — allocation-free) ----------------
__device__ int     g_is64;
__device__ int     g_cnt[N_NODES];
__device__ int     g_scan_state[NB];     // lookback: (value<<2)|status; 0=invalid,1=agg,2=prefix
__device__ int     g_rowoff[N_NODES + 1];
__device__ int     g_cursor[N_NODES];
__device__ int     g_sorted_src[N_EDGES];
__device__ __half2 g_packh[N_NODES * D]; // per (node,ch): half2(Q, R), Q=exp(-a_src-u), R=x_lin-u
__device__ float   g_agg[N_NODES * D];   // aggregated messages (pre out-proj)

// ---------------- f32x2 packed helpers ----------------
__device__ __forceinline__ unsigned long long pack2(float lo, float hi) {
    unsigned long long r;
    asm("mov.b64 %0, {%1, %2};" : "=l"(r) : "f"(lo), "f"(hi));
    return r;
}
__device__ __forceinline__ void unpack2(unsigned long long v, float& lo, float& hi) {
    asm("mov.b64 {%0, %1}, %2;" : "=f"(lo), "=f"(hi) : "l"(v));
}
__device__ __forceinline__ unsigned long long fma2(unsigned long long a,
                                                   unsigned long long b,
                                                   unsigned long long c) {
    unsigned long long d;
    asm("fma.rn.f32x2 %0, %1, %2, %3;" : "=l"(d) : "l"(a), "l"(b), "l"(c));
    return d;
}

__device__ __forceinline__ int load_idx(const void* eiv, int pos64) {
    if (g_is64) return (int)((const long long*)eiv)[pos64];
    return ((const int*)eiv)[pos64];
}

// ---------------- zero + edge-index dtype detection (fused) ----------------
__global__ void k_zero_cnt(const void* __restrict__ eiv) {
    int i = blockIdx.x * blockDim.x + threadIdx.x;
    if (i < N_NODES) g_cnt[i] = 0;
    if (i < NB) g_scan_state[i] = 0;
    if (i == 0) {
        const long long* p = (const long long*)eiv;
        int is64 = 1;
        for (int j = 0; j < 16; j++) {
            long long v = p[j];
            if (v < 0 || v >= (long long)N_NODES) is64 = 0;
        }
        g_is64 = is64;
    }
}

__global__ void k_hist(const void* __restrict__ eiv) {
    int e = blockIdx.x * blockDim.x + threadIdx.x;
    if (e < N_EDGES) {
        int d = load_idx(eiv, N_EDGES + e);
        if ((unsigned)d < (unsigned)N_NODES) atomicAdd(&g_cnt[d], 1);
    }
}

// ---------------- single-pass scan with decoupled lookback ----------------
// 98 blocks, all resident in one wave -> lookback spin is deadlock-free.
// values <= 1.25M fit in 30 bits, so (val<<2)|status packs into one int.
__global__ void k_scan_lookback() {
    __shared__ int warpsum[32];
    __shared__ int s_prefix;
    int t = threadIdx.x;
    int b = blockIdx.x;
    int i = b * 1024 + t;
    int v = (i < N_NODES) ? g_cnt[i] : 0;

    // block-wide inclusive scan (shuffle)
    int x = v;
#pragma unroll
    for (int o = 1; o < 32; o <<= 1) {
        int y = __shfl_up_sync(0xffffffffu, x, o);
        if ((t & 31) >= o) x += y;
    }
    if ((t & 31) == 31) warpsum[t >> 5] = x;
    __syncthreads();
    if (t < 32) {
        int w = warpsum[t];
#pragma unroll
        for (int o = 1; o < 32; o <<= 1) {
            int y = __shfl_up_sync(0xffffffffu, w, o);
            if (t >= o) w += y;
        }
        warpsum[t] = w;
    }
    __syncthreads();
    int wid = t >> 5;
    int incl = x + (wid ? warpsum[wid - 1] : 0);
    int block_agg = warpsum[31];

    // publish aggregate (block 0 publishes final prefix immediately)
    if (t == 0) {
        if (b == 0) {
            atomicExch(&g_scan_state[0], (block_agg << 2) | 2);
            s_prefix = 0;
        } else {
            atomicExch(&g_scan_state[b], (block_agg << 2) | 1);
            // lookback
            int sum = 0;
            int j = b - 1;
            while (j >= 0) {
                int s = atomicAdd(&g_scan_state[j], 0);
                int st = s & 3;
                if (st == 0) continue;        // spin until published
                sum += (s >> 2);
                if (st == 2) break;
                j--;
            }
            s_prefix = sum;
            atomicExch(&g_scan_state[b], ((sum + block_agg) << 2) | 2);
        }
    }
    __syncthreads();
    int pre = s_prefix;

    int off = pre + incl - v;   // exclusive prefix
    if (i < N_NODES) {
        g_rowoff[i] = off;
        g_cursor[i] = off;
    }
    if (i == N_NODES - 1) g_rowoff[N_NODES] = pre + incl;
}

__global__ void k_scatter(const void* __restrict__ eiv) {
    int e = blockIdx.x * blockDim.x + threadIdx.x;
    if (e < N_EDGES) {
        int d = load_idx(eiv, N_EDGES + e);
        int s = load_idx(eiv, e);
        if ((unsigned)d < (unsigned)N_NODES) {
            int p = atomicAdd(&g_cursor[d], 1);
            g_sorted_src[p] = ((unsigned)s < (unsigned)N_NODES) ? s : 0;
        }
    }
}

// ---------------- node projections + per-node softmax precompute ----------------
// h = relu(xW_in+b); Q = exp(-(h@W_src)-u), R = (h@W_lin)-u, u = pos@W_pos.
// (dst-side softmax terms cancel; W_dst is dead.) 16 nodes / 64-thread block —
// 16 FFMA2 per weight-pair makes the k-loop fma-pipe-bound, not issue-bound.
__global__ void k_nodeproj(const float* __restrict__ x, const float* __restrict__ pos,
                           const float* __restrict__ W_in, const float* __restrict__ b_in,
                           const float* __restrict__ W_lin, const float* __restrict__ W_src,
                           const float* __restrict__ W_pos) {
    __shared__ float sh[D][16];
    __shared__ float spos[48];
    int c = threadIdx.x;
    int n0 = blockIdx.x * 16;

#pragma unroll
    for (int r = 0; r < 16; r++) sh[c][r] = x[(n0 + r) * D + c];
    if (c < 48) spos[c] = pos[n0 * 3 + c];
    __syncthreads();

    float bi = b_in[c];
    unsigned long long hp[8];
#pragma unroll
    for (int p = 0; p < 8; p++) hp[p] = pack2(bi, bi);
#pragma unroll 4
    for (int k = 0; k < D; k++) {
        float w = W_in[k * D + c];
        unsigned long long ww = pack2(w, w);
#pragma unroll
        for (int p = 0; p < 8; p++) {
            unsigned long long xp = *(const unsigned long long*)&sh[k][2 * p];
            hp[p] = fma2(xp, ww, hp[p]);
        }
    }
    float h[16];
#pragma unroll
    for (int p = 0; p < 8; p++) {
        unpack2(hp[p], h[2 * p], h[2 * p + 1]);
        h[2 * p]     = fmaxf(h[2 * p], 0.0f);
        h[2 * p + 1] = fmaxf(h[2 * p + 1], 0.0f);
    }
    __syncthreads();
#pragma unroll
    for (int r = 0; r < 16; r++) sh[c][r] = h[r];
    __syncthreads();

    unsigned long long v1[8], v2[8];
#pragma unroll
    for (int p = 0; p < 8; p++) { v1[p] = 0ull; v2[p] = 0ull; }
#pragma unroll 4
    for (int k = 0; k < D; k++) {
        float w1 = W_lin[k * D + c];
        float w2 = W_src[k * D + c];
        unsigned long long ww1 = pack2(w1, w1);
        unsigned long long ww2 = pack2(w2, w2);
#pragma unroll
        for (int p = 0; p < 8; p++) {
            unsigned long long hpair = *(const unsigned long long*)&sh[k][2 * p];
            v1[p] = fma2(hpair, ww1, v1[p]);
            v2[p] = fma2(hpair, ww2, v2[p]);
        }
    }

    float wp0 = W_pos[0 * D + c], wp1 = W_pos[1 * D + c], wp2 = W_pos[2 * D + c];
#pragma unroll
    for (int p = 0; p < 8; p++) {
        float xl0, xl1, as0, as1;
        unpack2(v1[p], xl0, xl1);
        unpack2(v2[p], as0, as1);
        int na = n0 + 2 * p, nb = na + 1;
        float u0 = fmaf(spos[(2 * p) * 3 + 2], wp2,
                   fmaf(spos[(2 * p) * 3 + 1], wp1, spos[(2 * p) * 3 + 0] * wp0));
        float u1 = fmaf(spos[(2 * p + 1) * 3 + 2], wp2,
                   fmaf(spos[(2 * p + 1) * 3 + 1], wp1, spos[(2 * p + 1) * 3 + 0] * wp0));
        g_packh[na * D + c] = __floats2half2_rn(__expf(-as0 - u0), xl0 - u0);
        g_packh[nb * D + c] = __floats2half2_rn(__expf(-as1 - u1), xl1 - u1);
    }
}

// ---------------- edge pass: agg = (Σ Q·R)/(Σ Q) + (u[dst]+b_pos) ----------------
// warp per dst; lane owns channels {2*lane, 2*lane+1}; one coalesced 256-B warp
// transaction per edge. u[dst] recomputed on the fly (3 FMA, L1-resident W_pos).
__global__ void k_edge(const float* __restrict__ pos,
                       const float* __restrict__ W_pos, const float* __restrict__ b_pos) {
    int warp = threadIdx.x >> 5;
    int lane = threadIdx.x & 31;
    int dst = blockIdx.x * 4 + warp;
    if (dst >= N_NODES) return;

    int rs = g_rowoff[dst];
    int re = g_rowoff[dst + 1];

    float sq0 = 0.f, sr0 = 0.f, sq1 = 0.f, sr1 = 0.f;

    for (int base = rs; base < re; base += 32) {
        int m = min(32, re - base);
        int idx = (lane < m) ? g_sorted_src[base + lane] : 0;
        int j = 0;
        for (; j + 2 <= m; j += 2) {
            int s0 = __shfl_sync(0xffffffffu, idx, j);
            int s1 = __shfl_sync(0xffffffffu, idx, j + 1);
            uint2 v0 = *reinterpret_cast<const uint2*>(&g_packh[s0 * D + 2 * lane]);
            uint2 v1 = *reinterpret_cast<const uint2*>(&g_packh[s1 * D + 2 * lane]);
            float2 a0 = __half22float2(*reinterpret_cast<const __half2*>(&v0.x));
            float2 b0 = __half22float2(*reinterpret_cast<const __half2*>(&v0.y));
            float2 a1 = __half22float2(*reinterpret_cast<const __half2*>(&v1.x));
            float2 b1 = __half22float2(*reinterpret_cast<const __half2*>(&v1.y));
            sq0 += a0.x; sr0 = fmaf(a0.x, a0.y, sr0);
            sq1 += b0.x; sr1 = fmaf(b0.x, b0.y, sr1);
            sq0 += a1.x; sr0 = fmaf(a1.x, a1.y, sr0);
            sq1 += b1.x; sr1 = fmaf(b1.x, b1.y, sr1);
        }
        if (j < m) {
            int s0 = __shfl_sync(0xffffffffu, idx, j);
            uint2 v0 = *reinterpret_cast<const uint2*>(&g_packh[s0 * D + 2 * lane]);
            float2 a0 = __half22float2(*reinterpret_cast<const __half2*>(&v0.x));
            float2 b0 = __half22float2(*reinterpret_cast<const __half2*>(&v0.y));
            sq0 += a0.x; sr0 = fmaf(a0.x, a0.y, sr0);
            sq1 += b0.x; sr1 = fmaf(b0.x, b0.y, sr1);
        }
    }

    int c0 = 2 * lane;
    if (re > rs) {
        float p0 = pos[dst * 3 + 0], p1 = pos[dst * 3 + 1], p2 = pos[dst * 3 + 2];
        float u0 = fmaf(p2, W_pos[2 * D + c0],     fmaf(p1, W_pos[1 * D + c0],     p0 * W_pos[0 * D + c0]));
        float u1 = fmaf(p2, W_pos[2 * D + c0 + 1], fmaf(p1, W_pos[1 * D + c0 + 1], p0 * W_pos[0 * D + c0 + 1]));
        g_agg[dst * D + c0]     = sr0 / sq0 + u0 + b_pos[c0];
        g_agg[dst * D + c0 + 1] = sr1 / sq1 + u1 + b_pos[c0 + 1];
    } else {
        g_agg[dst * D + c0]     = 0.0f;
        g_agg[dst * D + c0 + 1] = 0.0f;
    }
}

// ---------------- out projection: out = relu(agg @ W_out + b_out) ----------------
__global__ void k_outproj(const float* __restrict__ W_out, const float* __restrict__ b_out,
                          float* __restrict__ out) {
    __shared__ float sh[D][16];
    int c = threadIdx.x;
    int n0 = blockIdx.x * 16;

#pragma unroll
    for (int r = 0; r < 16; r++) sh[c][r] = g_agg[(n0 + r) * D + c];
    __syncthreads();

    float bo = b_out[c];
    unsigned long long op[8];
#pragma unroll
    for (int p = 0; p < 8; p++) op[p] = pack2(bo, bo);
#pragma unroll 4
    for (int k = 0; k < D; k++) {
        float w = W_out[k * D + c];
        unsigned long long ww = pack2(w, w);
#pragma unroll
        for (int p = 0; p < 8; p++) {
            unsigned long long ap = *(const unsigned long long*)&sh[k][2 * p];
            op[p] = fma2(ap, ww, op[p]);
        }
    }
#pragma unroll
    for (int p = 0; p < 8; p++) {
        float o0, o1;
        unpack2(op[p], o0, o1);
        out[(n0 + 2 * p) * D + c]     = fmaxf(o0, 0.0f);
        out[(n0 + 2 * p + 1) * D + c] = fmaxf(o1, 0.0f);
    }
}

// ---------------- launch ----------------
extern "C" void kernel_launch(void* const* d_in, const int* in_sizes, int n_in,
                              void* d_out, int out_size) {
    const float* x     = (const float*)d_in[0];
    const float* pos   = (const float*)d_in[1];
    const void*  ei    = d_in[2];
    const float* W_in  = (const float*)d_in[3];
    const float* b_in  = (const float*)d_in[4];
    const float* W_lin = (const float*)d_in[5];
    const float* W_src = (const float*)d_in[6];
    // d_in[7] = W_dst: dead (dst-side softmax terms cancel)
    const float* W_pos = (const float*)d_in[8];
    const float* b_pos = (const float*)d_in[9];
    const float* W_out = (const float*)d_in[10];
    const float* b_out = (const float*)d_in[11];
    float* out = (float*)d_out;

    k_zero_cnt<<<(N_NODES + 255) / 256, 256>>>(ei);
    k_hist<<<(N_EDGES + 255) / 256, 256>>>(ei);
    k_scan_lookback<<<NB, 1024>>>();
    k_scatter<<<(N_EDGES + 255) / 256, 256>>>(ei);
    k_nodeproj<<<N_NODES / 16, 64>>>(x, pos, W_in, b_in, W_lin, W_src, W_pos);
    k_edge<<<(N_NODES + 3) / 4, 128>>>(pos, W_pos, b_pos);
    k_outproj<<<N_NODES / 16, 64>>>(W_out, b_out, out);
}

// round 7
// speedup vs baseline: 1.0007x; 1.0007x over previous
#include <cuda_runtime.h>
#include <cuda_fp16.h>

#define N_NODES 100000
#define N_EDGES 1250000
#define D 64
#define NB 98          // scan blocks: ceil(N/1024)
#define PAD 18         // smem row stride (floats): 8B-aligned, conflict-light

// ---------------- scratch (static __device__ — allocation-free) ----------------
__device__ int     g_is64;
__device__ int     g_cnt[N_NODES];       // statics are zero-initialized; scan re-zeroes each run
__device__ int     g_scan_state[NB];     // lookback: (value<<2)|status; 0=invalid,1=agg,2=prefix
__device__ int     g_rowoff[N_NODES + 1];
__device__ int     g_cursor[N_NODES];
__device__ int     g_sorted_src[N_EDGES];
__device__ __half2 g_packh[N_NODES * D]; // per (node,ch): half2(Q, R), Q=exp(-a_src-u), R=x_lin-u
__device__ float   g_agg[N_NODES * D];   // aggregated messages (pre out-proj)

// ---------------- f32x2 packed helpers ----------------
__device__ __forceinline__ unsigned long long pack2(float lo, float hi) {
    unsigned long long r;
    asm("mov.b64 %0, {%1, %2};" : "=l"(r) : "f"(lo), "f"(hi));
    return r;
}
__device__ __forceinline__ void unpack2(unsigned long long v, float& lo, float& hi) {
    asm("mov.b64 {%0, %1}, %2;" : "=f"(lo), "=f"(hi) : "l"(v));
}
__device__ __forceinline__ unsigned long long fma2(unsigned long long a,
                                                   unsigned long long b,
                                                   unsigned long long c) {
    unsigned long long d;
    asm("fma.rn.f32x2 %0, %1, %2, %3;" : "=l"(d) : "l"(a), "l"(b), "l"(c));
    return d;
}

__device__ __forceinline__ int load_idx(const void* eiv, int pos64) {
    if (g_is64) return (int)((const long long*)eiv)[pos64];
    return ((const int*)eiv)[pos64];
}

// ---------------- init: dtype detect + zero the 98 lookback states ----------------
__global__ void k_init(const void* __restrict__ eiv) {
    int t = threadIdx.x;
    if (t < NB) g_scan_state[t] = 0;
    if (t == 0) {
        const long long* p = (const long long*)eiv;
        int is64 = 1;
        for (int j = 0; j < 16; j++) {
            long long v = p[j];
            if (v < 0 || v >= (long long)N_NODES) is64 = 0;
        }
        g_is64 = is64;
    }
}

__global__ void k_hist(const void* __restrict__ eiv) {
    int e = blockIdx.x * blockDim.x + threadIdx.x;
    if (e < N_EDGES) {
        int d = load_idx(eiv, N_EDGES + e);
        if ((unsigned)d < (unsigned)N_NODES) atomicAdd(&g_cnt[d], 1);
    }
}

// ---------------- single-pass scan with decoupled lookback ----------------
// 98 blocks (one wave) -> spin is deadlock-free. Self-zeroes g_cnt for the
// next graph replay (each element is read exactly once, by its own block).
__global__ void k_scan_lookback() {
    __shared__ int warpsum[32];
    __shared__ int s_prefix;
    int t = threadIdx.x;
    int b = blockIdx.x;
    int i = b * 1024 + t;
    int v = (i < N_NODES) ? g_cnt[i] : 0;
    if (i < N_NODES) g_cnt[i] = 0;

    int x = v;
#pragma unroll
    for (int o = 1; o < 32; o <<= 1) {
        int y = __shfl_up_sync(0xffffffffu, x, o);
        if ((t & 31) >= o) x += y;
    }
    if ((t & 31) == 31) warpsum[t >> 5] = x;
    __syncthreads();
    if (t < 32) {
        int w = warpsum[t];
#pragma unroll
        for (int o = 1; o < 32; o <<= 1) {
            int y = __shfl_up_sync(0xffffffffu, w, o);
            if (t >= o) w += y;
        }
        warpsum[t] = w;
    }
    __syncthreads();
    int wid = t >> 5;
    int incl = x + (wid ? warpsum[wid - 1] : 0);
    int block_agg = warpsum[31];

    if (t == 0) {
        if (b == 0) {
            atomicExch(&g_scan_state[0], (block_agg << 2) | 2);
            s_prefix = 0;
        } else {
            atomicExch(&g_scan_state[b], (block_agg << 2) | 1);
            int sum = 0;
            int j = b - 1;
            while (j >= 0) {
                int s = atomicAdd(&g_scan_state[j], 0);
                int st = s & 3;
                if (st == 0) continue;
                sum += (s >> 2);
                if (st == 2) break;
                j--;
            }
            s_prefix = sum;
            atomicExch(&g_scan_state[b], ((sum + block_agg) << 2) | 2);
        }
    }
    __syncthreads();
    int pre = s_prefix;

    int off = pre + incl - v;
    if (i < N_NODES) {
        g_rowoff[i] = off;
        g_cursor[i] = off;
    }
    if (i == N_NODES - 1) g_rowoff[N_NODES] = pre + incl;
}

__global__ void k_scatter(const void* __restrict__ eiv) {
    int e = blockIdx.x * blockDim.x + threadIdx.x;
    if (e < N_EDGES) {
        int d = load_idx(eiv, N_EDGES + e);
        int s = load_idx(eiv, e);
        if ((unsigned)d < (unsigned)N_NODES) {
            int p = atomicAdd(&g_cursor[d], 1);
            g_sorted_src[p] = ((unsigned)s < (unsigned)N_NODES) ? s : 0;
        }
    }
}

// ---------------- node projections + per-node softmax precompute ----------------
// h = relu(xW_in+b); Q = exp(-(h@W_src)-u), R = (h@W_lin)-u, u = pos@W_pos.
// 16 nodes / 64-thread block, f32x2 packed, PAD-strided smem (conflict-free-ish).
__global__ void k_nodeproj(const float* __restrict__ x, const float* __restrict__ pos,
                           const float* __restrict__ W_in, const float* __restrict__ b_in,
                           const float* __restrict__ W_lin, const float* __restrict__ W_src,
                           const float* __restrict__ W_pos) {
    __shared__ float sh[D][PAD];
    __shared__ float spos[48];
    int c = threadIdx.x;
    int n0 = blockIdx.x * 16;

#pragma unroll
    for (int r = 0; r < 16; r++) sh[c][r] = x[(n0 + r) * D + c];
    if (c < 48) spos[c] = pos[n0 * 3 + c];
    __syncthreads();

    float bi = b_in[c];
    unsigned long long hp[8];
#pragma unroll
    for (int p = 0; p < 8; p++) hp[p] = pack2(bi, bi);
#pragma unroll 4
    for (int k = 0; k < D; k++) {
        float w = W_in[k * D + c];
        unsigned long long ww = pack2(w, w);
#pragma unroll
        for (int p = 0; p < 8; p++) {
            unsigned long long xp = *(const unsigned long long*)&sh[k][2 * p];
            hp[p] = fma2(xp, ww, hp[p]);
        }
    }
    float h[16];
#pragma unroll
    for (int p = 0; p < 8; p++) {
        unpack2(hp[p], h[2 * p], h[2 * p + 1]);
        h[2 * p]     = fmaxf(h[2 * p], 0.0f);
        h[2 * p + 1] = fmaxf(h[2 * p + 1], 0.0f);
    }
    __syncthreads();
#pragma unroll
    for (int r = 0; r < 16; r++) sh[c][r] = h[r];
    __syncthreads();

    unsigned long long v1[8], v2[8];
#pragma unroll
    for (int p = 0; p < 8; p++) { v1[p] = 0ull; v2[p] = 0ull; }
#pragma unroll 4
    for (int k = 0; k < D; k++) {
        float w1 = W_lin[k * D + c];
        float w2 = W_src[k * D + c];
        unsigned long long ww1 = pack2(w1, w1);
        unsigned long long ww2 = pack2(w2, w2);
#pragma unroll
        for (int p = 0; p < 8; p++) {
            unsigned long long hpair = *(const unsigned long long*)&sh[k][2 * p];
            v1[p] = fma2(hpair, ww1, v1[p]);
            v2[p] = fma2(hpair, ww2, v2[p]);
        }
    }

    float wp0 = W_pos[0 * D + c], wp1 = W_pos[1 * D + c], wp2 = W_pos[2 * D + c];
#pragma unroll
    for (int p = 0; p < 8; p++) {
        float xl0, xl1, as0, as1;
        unpack2(v1[p], xl0, xl1);
        unpack2(v2[p], as0, as1);
        int na = n0 + 2 * p, nb = na + 1;
        float u0 = fmaf(spos[(2 * p) * 3 + 2], wp2,
                   fmaf(spos[(2 * p) * 3 + 1], wp1, spos[(2 * p) * 3 + 0] * wp0));
        float u1 = fmaf(spos[(2 * p + 1) * 3 + 2], wp2,
                   fmaf(spos[(2 * p + 1) * 3 + 1], wp1, spos[(2 * p + 1) * 3 + 0] * wp0));
        g_packh[na * D + c] = __floats2half2_rn(__expf(-as0 - u0), xl0 - u0);
        g_packh[nb * D + c] = __floats2half2_rn(__expf(-as1 - u1), xl1 - u1);
    }
}

// ---------------- edge pass: agg = (Σ Q·R)/(Σ Q) + (u[dst]+b_pos) ----------------
// warp per dst (8 dst / 256-thread block); lane owns channels {2l, 2l+1}.
// One coalesced 256-B warp gather per edge; unroll 4 for MLP against L2 latency.
__global__ void k_edge(const float* __restrict__ pos,
                       const float* __restrict__ W_pos, const float* __restrict__ b_pos) {
    int warp = threadIdx.x >> 5;
    int lane = threadIdx.x & 31;
    int dst = blockIdx.x * 8 + warp;
    if (dst >= N_NODES) return;

    int rs = g_rowoff[dst];
    int re = g_rowoff[dst + 1];

    float sq0 = 0.f, sr0 = 0.f, sq1 = 0.f, sr1 = 0.f;

    for (int base = rs; base < re; base += 32) {
        int m = min(32, re - base);
        int idx = (lane < m) ? g_sorted_src[base + lane] : 0;
        int j = 0;
        for (; j + 4 <= m; j += 4) {
            int s0 = __shfl_sync(0xffffffffu, idx, j);
            int s1 = __shfl_sync(0xffffffffu, idx, j + 1);
            int s2 = __shfl_sync(0xffffffffu, idx, j + 2);
            int s3 = __shfl_sync(0xffffffffu, idx, j + 3);
            uint2 v0 = *reinterpret_cast<const uint2*>(&g_packh[s0 * D + 2 * lane]);
            uint2 v1 = *reinterpret_cast<const uint2*>(&g_packh[s1 * D + 2 * lane]);
            uint2 v2 = *reinterpret_cast<const uint2*>(&g_packh[s2 * D + 2 * lane]);
            uint2 v3 = *reinterpret_cast<const uint2*>(&g_packh[s3 * D + 2 * lane]);
            float2 a0 = __half22float2(*reinterpret_cast<const __half2*>(&v0.x));
            float2 b0 = __half22float2(*reinterpret_cast<const __half2*>(&v0.y));
            float2 a1 = __half22float2(*reinterpret_cast<const __half2*>(&v1.x));
            float2 b1 = __half22float2(*reinterpret_cast<const __half2*>(&v1.y));
            float2 a2 = __half22float2(*reinterpret_cast<const __half2*>(&v2.x));
            float2 b2 = __half22float2(*reinterpret_cast<const __half2*>(&v2.y));
            float2 a3 = __half22float2(*reinterpret_cast<const __half2*>(&v3.x));
            float2 b3 = __half22float2(*reinterpret_cast<const __half2*>(&v3.y));
            sq0 += a0.x; sr0 = fmaf(a0.x, a0.y, sr0);
            sq1 += b0.x; sr1 = fmaf(b0.x, b0.y, sr1);
            sq0 += a1.x; sr0 = fmaf(a1.x, a1.y, sr0);
            sq1 += b1.x; sr1 = fmaf(b1.x, b1.y, sr1);
            sq0 += a2.x; sr0 = fmaf(a2.x, a2.y, sr0);
            sq1 += b2.x; sr1 = fmaf(b2.x, b2.y, sr1);
            sq0 += a3.x; sr0 = fmaf(a3.x, a3.y, sr0);
            sq1 += b3.x; sr1 = fmaf(b3.x, b3.y, sr1);
        }
        for (; j < m; j++) {
            int s0 = __shfl_sync(0xffffffffu, idx, j);
            uint2 v0 = *reinterpret_cast<const uint2*>(&g_packh[s0 * D + 2 * lane]);
            float2 a0 = __half22float2(*reinterpret_cast<const __half2*>(&v0.x));
            float2 b0 = __half22float2(*reinterpret_cast<const __half2*>(&v0.y));
            sq0 += a0.x; sr0 = fmaf(a0.x, a0.y, sr0);
            sq1 += b0.x; sr1 = fmaf(b0.x, b0.y, sr1);
        }
    }

    int c0 = 2 * lane;
    if (re > rs) {
        float p0 = pos[dst * 3 + 0], p1 = pos[dst * 3 + 1], p2 = pos[dst * 3 + 2];
        float u0 = fmaf(p2, W_pos[2 * D + c0],     fmaf(p1, W_pos[1 * D + c0],     p0 * W_pos[0 * D + c0]));
        float u1 = fmaf(p2, W_pos[2 * D + c0 + 1], fmaf(p1, W_pos[1 * D + c0 + 1], p0 * W_pos[0 * D + c0 + 1]));
        g_agg[dst * D + c0]     = sr0 / sq0 + u0 + b_pos[c0];
        g_agg[dst * D + c0 + 1] = sr1 / sq1 + u1 + b_pos[c0 + 1];
    } else {
        g_agg[dst * D + c0]     = 0.0f;
        g_agg[dst * D + c0 + 1] = 0.0f;
    }
}

// ---------------- out projection: out = relu(agg @ W_out + b_out) ----------------
__global__ void k_outproj(const float* __restrict__ W_out, const float* __restrict__ b_out,
                          float* __restrict__ out) {
    __shared__ float sh[D][PAD];
    int c = threadIdx.x;
    int n0 = blockIdx.x * 16;

#pragma unroll
    for (int r = 0; r < 16; r++) sh[c][r] = g_agg[(n0 + r) * D + c];
    __syncthreads();

    float bo = b_out[c];
    unsigned long long op[8];
#pragma unroll
    for (int p = 0; p < 8; p++) op[p] = pack2(bo, bo);
#pragma unroll 4
    for (int k = 0; k < D; k++) {
        float w = W_out[k * D + c];
        unsigned long long ww = pack2(w, w);
#pragma unroll
        for (int p = 0; p < 8; p++) {
            unsigned long long ap = *(const unsigned long long*)&sh[k][2 * p];
            op[p] = fma2(ap, ww, op[p]);
        }
    }
#pragma unroll
    for (int p = 0; p < 8; p++) {
        float o0, o1;
        unpack2(op[p], o0, o1);
        out[(n0 + 2 * p) * D + c]     = fmaxf(o0, 0.0f);
        out[(n0 + 2 * p + 1) * D + c] = fmaxf(o1, 0.0f);
    }
}

// ---------------- launch ----------------
extern "C" void kernel_launch(void* const* d_in, const int* in_sizes, int n_in,
                              void* d_out, int out_size) {
    const float* x     = (const float*)d_in[0];
    const float* pos   = (const float*)d_in[1];
    const void*  ei    = d_in[2];
    const float* W_in  = (const float*)d_in[3];
    const float* b_in  = (const float*)d_in[4];
    const float* W_lin = (const float*)d_in[5];
    const float* W_src = (const float*)d_in[6];
    // d_in[7] = W_dst: dead (dst-side softmax terms cancel)
    const float* W_pos = (const float*)d_in[8];
    const float* b_pos = (const float*)d_in[9];
    const float* W_out = (const float*)d_in[10];
    const float* b_out = (const float*)d_in[11];
    float* out = (float*)d_out;

    k_init<<<1, 128>>>(ei);
    k_hist<<<(N_EDGES + 255) / 256, 256>>>(ei);
    k_scan_lookback<<<NB, 1024>>>();
    k_scatter<<<(N_EDGES + 255) / 256, 256>>>(ei);
    k_nodeproj<<<N_NODES / 16, 64>>>(x, pos, W_in, b_in, W_lin, W_src, W_pos);
    k_edge<<<(N_NODES + 7) / 8, 256>>>(pos, W_pos, b_pos);
    k_outproj<<<N_NODES / 16, 64>>>(W_out, b_out, out);
}

// round 8
// speedup vs baseline: 1.0439x; 1.0432x over previous
#include <cuda_runtime.h>
#include <cuda_fp16.h>

#define N_NODES 100000
#define N_EDGES 1250000
#define D 64
#define NB 98          // scan blocks: ceil(N/1024)
#define PAD 18         // smem row stride (floats): 8B-aligned, conflict-light
#define NPB 6250       // nodeproj blocks (N/16)
#define EPB 200        // hist edges per nodeproj block (E/NPB)

// ---------------- scratch (static __device__ — allocation-free) ----------------
__device__ int     g_cnt[N_NODES];       // zero-init; k_scan re-zeroes after reading
__device__ int     g_scan_state[NB];     // lookback state; k_scatter re-zeroes for next replay
__device__ int     g_rowoff[N_NODES + 1];
__device__ int     g_cursor[N_NODES];
__device__ int     g_sorted_src[N_EDGES];
__device__ __half2 g_packh[N_NODES * D]; // per (node,ch): half2(Q, R), Q=exp(-a_src-u), R=x_lin-u
__device__ float   g_agg[N_NODES * D];   // aggregated messages (pre out-proj)

// ---------------- f32x2 packed helpers ----------------
__device__ __forceinline__ unsigned long long pack2(float lo, float hi) {
    unsigned long long r;
    asm("mov.b64 %0, {%1, %2};" : "=l"(r) : "f"(lo), "f"(hi));
    return r;
}
__device__ __forceinline__ void unpack2(unsigned long long v, float& lo, float& hi) {
    asm("mov.b64 {%0, %1}, %2;" : "=f"(lo), "=f"(hi) : "l"(v));
}
__device__ __forceinline__ unsigned long long fma2(unsigned long long a,
                                                   unsigned long long b,
                                                   unsigned long long c) {
    unsigned long long d;
    asm("fma.rn.f32x2 %0, %1, %2, %3;" : "=l"(d) : "l"(a), "l"(b), "l"(c));
    return d;
}

// int64-vs-int32 edge dtype probe (first 16 entries; int32 data read as int64
// exceeds [0,N) with overwhelming probability)
__device__ __forceinline__ int detect_is64(const void* eiv) {
    const long long* p = (const long long*)eiv;
    int is64 = 1;
#pragma unroll
    for (int j = 0; j < 16; j++) {
        long long v = p[j];
        if (v < 0 || v >= (long long)N_NODES) is64 = 0;
    }
    return is64;
}

__device__ __forceinline__ int load_idx(const void* eiv, int pos64, int is64) {
    if (is64) return (int)((const long long*)eiv)[pos64];
    return ((const int*)eiv)[pos64];
}

// ---------------- fused: node projections + hist slice ----------------
// nodeproj: h = relu(xW_in+b); Q = exp(-(h@W_src)-u), R = (h@W_lin)-u, u = pos@W_pos
// (dst-side softmax terms cancel; W_dst dead). 16 nodes / 64-thread block.
// hist: each block also counts a 200-edge slice (atomics overlap the FMA phase).
__global__ void k_nodehist(const void* __restrict__ eiv,
                           const float* __restrict__ x, const float* __restrict__ pos,
                           const float* __restrict__ W_in, const float* __restrict__ b_in,
                           const float* __restrict__ W_lin, const float* __restrict__ W_src,
                           const float* __restrict__ W_pos) {
    __shared__ float sh[D][PAD];
    __shared__ float spos[48];
    __shared__ int sflag;
    int c = threadIdx.x;
    int n0 = blockIdx.x * 16;

#pragma unroll
    for (int r = 0; r < 16; r++) sh[c][r] = x[(n0 + r) * D + c];
    if (c < 48) spos[c] = pos[n0 * 3 + c];
    if (c == 0) sflag = detect_is64(eiv);
    __syncthreads();

    // ---- hist slice (RED atomics, fire-and-forget; hidden under GEMM) ----
    {
        int is64 = sflag;
        int base = blockIdx.x * EPB;
#pragma unroll
        for (int e = base + c; e < base + EPB; e += 64) {
            int d = load_idx(eiv, N_EDGES + e, is64);
            if ((unsigned)d < (unsigned)N_NODES) atomicAdd(&g_cnt[d], 1);
        }
    }

    // ---- GEMM 1: h = relu(x @ W_in + b_in) ----
    float bi = b_in[c];
    unsigned long long hp[8];
#pragma unroll
    for (int p = 0; p < 8; p++) hp[p] = pack2(bi, bi);
#pragma unroll 4
    for (int k = 0; k < D; k++) {
        float w = W_in[k * D + c];
        unsigned long long ww = pack2(w, w);
#pragma unroll
        for (int p = 0; p < 8; p++) {
            unsigned long long xp = *(const unsigned long long*)&sh[k][2 * p];
            hp[p] = fma2(xp, ww, hp[p]);
        }
    }
    float h[16];
#pragma unroll
    for (int p = 0; p < 8; p++) {
        unpack2(hp[p], h[2 * p], h[2 * p + 1]);
        h[2 * p]     = fmaxf(h[2 * p], 0.0f);
        h[2 * p + 1] = fmaxf(h[2 * p + 1], 0.0f);
    }
    __syncthreads();
#pragma unroll
    for (int r = 0; r < 16; r++) sh[c][r] = h[r];
    __syncthreads();

    // ---- GEMMs 2+3: x_lin = h@W_lin, a_src = h@W_src ----
    unsigned long long v1[8], v2[8];
#pragma unroll
    for (int p = 0; p < 8; p++) { v1[p] = 0ull; v2[p] = 0ull; }
#pragma unroll 4
    for (int k = 0; k < D; k++) {
        float w1 = W_lin[k * D + c];
        float w2 = W_src[k * D + c];
        unsigned long long ww1 = pack2(w1, w1);
        unsigned long long ww2 = pack2(w2, w2);
#pragma unroll
        for (int p = 0; p < 8; p++) {
            unsigned long long hpair = *(const unsigned long long*)&sh[k][2 * p];
            v1[p] = fma2(hpair, ww1, v1[p]);
            v2[p] = fma2(hpair, ww2, v2[p]);
        }
    }

    float wp0 = W_pos[0 * D + c], wp1 = W_pos[1 * D + c], wp2 = W_pos[2 * D + c];
#pragma unroll
    for (int p = 0; p < 8; p++) {
        float xl0, xl1, as0, as1;
        unpack2(v1[p], xl0, xl1);
        unpack2(v2[p], as0, as1);
        int na = n0 + 2 * p, nb = na + 1;
        float u0 = fmaf(spos[(2 * p) * 3 + 2], wp2,
                   fmaf(spos[(2 * p) * 3 + 1], wp1, spos[(2 * p) * 3 + 0] * wp0));
        float u1 = fmaf(spos[(2 * p + 1) * 3 + 2], wp2,
                   fmaf(spos[(2 * p + 1) * 3 + 1], wp1, spos[(2 * p + 1) * 3 + 0] * wp0));
        g_packh[na * D + c] = __floats2half2_rn(__expf(-as0 - u0), xl0 - u0);
        g_packh[nb * D + c] = __floats2half2_rn(__expf(-as1 - u1), xl1 - u1);
    }
}

// ---------------- single-pass scan with decoupled lookback ----------------
// 98 blocks (one wave) -> spin is deadlock-free. Self-zeroes g_cnt after
// reading (each element read exactly once, by its own block).
__global__ void k_scan_lookback() {
    __shared__ int warpsum[32];
    __shared__ int s_prefix;
    int t = threadIdx.x;
    int b = blockIdx.x;
    int i = b * 1024 + t;
    int v = (i < N_NODES) ? g_cnt[i] : 0;
    if (i < N_NODES) g_cnt[i] = 0;

    int x = v;
#pragma unroll
    for (int o = 1; o < 32; o <<= 1) {
        int y = __shfl_up_sync(0xffffffffu, x, o);
        if ((t & 31) >= o) x += y;
    }
    if ((t & 31) == 31) warpsum[t >> 5] = x;
    __syncthreads();
    if (t < 32) {
        int w = warpsum[t];
#pragma unroll
        for (int o = 1; o < 32; o <<= 1) {
            int y = __shfl_up_sync(0xffffffffu, w, o);
            if (t >= o) w += y;
        }
        warpsum[t] = w;
    }
    __syncthreads();
    int wid = t >> 5;
    int incl = x + (wid ? warpsum[wid - 1] : 0);
    int block_agg = warpsum[31];

    if (t == 0) {
        if (b == 0) {
            atomicExch(&g_scan_state[0], (block_agg << 2) | 2);
            s_prefix = 0;
        } else {
            atomicExch(&g_scan_state[b], (block_agg << 2) | 1);
            int sum = 0;
            int j = b - 1;
            while (j >= 0) {
                int s = atomicAdd(&g_scan_state[j], 0);
                int st = s & 3;
                if (st == 0) continue;
                sum += (s >> 2);
                if (st == 2) break;
                j--;
            }
            s_prefix = sum;
            atomicExch(&g_scan_state[b], ((sum + block_agg) << 2) | 2);
        }
    }
    __syncthreads();
    int pre = s_prefix;

    int off = pre + incl - v;
    if (i < N_NODES) {
        g_rowoff[i] = off;
        g_cursor[i] = off;
    }
    if (i == N_NODES - 1) g_rowoff[N_NODES] = pre + incl;
}

// ---------------- scatter (also re-zeroes scan state for next replay) ----------------
__global__ void k_scatter(const void* __restrict__ eiv) {
    __shared__ int sflag;
    if (threadIdx.x == 0) sflag = detect_is64(eiv);
    __syncthreads();
    int is64 = sflag;

    int e = blockIdx.x * blockDim.x + threadIdx.x;
    if (blockIdx.x == 0 && threadIdx.x < NB) g_scan_state[threadIdx.x] = 0;
    if (e < N_EDGES) {
        int d = load_idx(eiv, N_EDGES + e, is64);
        int s = load_idx(eiv, e, is64);
        if ((unsigned)d < (unsigned)N_NODES) {
            int p = atomicAdd(&g_cursor[d], 1);
            g_sorted_src[p] = ((unsigned)s < (unsigned)N_NODES) ? s : 0;
        }
    }
}

// ---------------- edge pass: agg = (Σ Q·R)/(Σ Q) + (u[dst]+b_pos) ----------------
// warp per dst (8 dst / 256-thread block); lane owns channels {2l, 2l+1}.
// One coalesced 256-B warp gather per edge; unroll 4 for MLP against L2 latency.
__global__ void k_edge(const float* __restrict__ pos,
                       const float* __restrict__ W_pos, const float* __restrict__ b_pos) {
    int warp = threadIdx.x >> 5;
    int lane = threadIdx.x & 31;
    int dst = blockIdx.x * 8 + warp;
    if (dst >= N_NODES) return;

    int rs = g_rowoff[dst];
    int re = g_rowoff[dst + 1];

    float sq0 = 0.f, sr0 = 0.f, sq1 = 0.f, sr1 = 0.f;

    for (int base = rs; base < re; base += 32) {
        int m = min(32, re - base);
        int idx = (lane < m) ? g_sorted_src[base + lane] : 0;
        int j = 0;
        for (; j + 4 <= m; j += 4) {
            int s0 = __shfl_sync(0xffffffffu, idx, j);
            int s1 = __shfl_sync(0xffffffffu, idx, j + 1);
            int s2 = __shfl_sync(0xffffffffu, idx, j + 2);
            int s3 = __shfl_sync(0xffffffffu, idx, j + 3);
            uint2 v0 = *reinterpret_cast<const uint2*>(&g_packh[s0 * D + 2 * lane]);
            uint2 v1 = *reinterpret_cast<const uint2*>(&g_packh[s1 * D + 2 * lane]);
            uint2 v2 = *reinterpret_cast<const uint2*>(&g_packh[s2 * D + 2 * lane]);
            uint2 v3 = *reinterpret_cast<const uint2*>(&g_packh[s3 * D + 2 * lane]);
            float2 a0 = __half22float2(*reinterpret_cast<const __half2*>(&v0.x));
            float2 b0 = __half22float2(*reinterpret_cast<const __half2*>(&v0.y));
            float2 a1 = __half22float2(*reinterpret_cast<const __half2*>(&v1.x));
            float2 b1 = __half22float2(*reinterpret_cast<const __half2*>(&v1.y));
            float2 a2 = __half22float2(*reinterpret_cast<const __half2*>(&v2.x));
            float2 b2 = __half22float2(*reinterpret_cast<const __half2*>(&v2.y));
            float2 a3 = __half22float2(*reinterpret_cast<const __half2*>(&v3.x));
            float2 b3 = __half22float2(*reinterpret_cast<const __half2*>(&v3.y));
            sq0 += a0.x; sr0 = fmaf(a0.x, a0.y, sr0);
            sq1 += b0.x; sr1 = fmaf(b0.x, b0.y, sr1);
            sq0 += a1.x; sr0 = fmaf(a1.x, a1.y, sr0);
            sq1 += b1.x; sr1 = fmaf(b1.x, b1.y, sr1);
            sq0 += a2.x; sr0 = fmaf(a2.x, a2.y, sr0);
            sq1 += b2.x; sr1 = fmaf(b2.x, b2.y, sr1);
            sq0 += a3.x; sr0 = fmaf(a3.x, a3.y, sr0);
            sq1 += b3.x; sr1 = fmaf(b3.x, b3.y, sr1);
        }
        for (; j < m; j++) {
            int s0 = __shfl_sync(0xffffffffu, idx, j);
            uint2 v0 = *reinterpret_cast<const uint2*>(&g_packh[s0 * D + 2 * lane]);
            float2 a0 = __half22float2(*reinterpret_cast<const __half2*>(&v0.x));
            float2 b0 = __half22float2(*reinterpret_cast<const __half2*>(&v0.y));
            sq0 += a0.x; sr0 = fmaf(a0.x, a0.y, sr0);
            sq1 += b0.x; sr1 = fmaf(b0.x, b0.y, sr1);
        }
    }

    int c0 = 2 * lane;
    if (re > rs) {
        float p0 = pos[dst * 3 + 0], p1 = pos[dst * 3 + 1], p2 = pos[dst * 3 + 2];
        float u0 = fmaf(p2, W_pos[2 * D + c0],     fmaf(p1, W_pos[1 * D + c0],     p0 * W_pos[0 * D + c0]));
        float u1 = fmaf(p2, W_pos[2 * D + c0 + 1], fmaf(p1, W_pos[1 * D + c0 + 1], p0 * W_pos[0 * D + c0 + 1]));
        g_agg[dst * D + c0]     = sr0 / sq0 + u0 + b_pos[c0];
        g_agg[dst * D + c0 + 1] = sr1 / sq1 + u1 + b_pos[c0 + 1];
    } else {
        g_agg[dst * D + c0]     = 0.0f;
        g_agg[dst * D + c0 + 1] = 0.0f;
    }
}

// ---------------- out projection: out = relu(agg @ W_out + b_out) ----------------
__global__ void k_outproj(const float* __restrict__ W_out, const float* __restrict__ b_out,
                          float* __restrict__ out) {
    __shared__ float sh[D][PAD];
    int c = threadIdx.x;
    int n0 = blockIdx.x * 16;

#pragma unroll
    for (int r = 0; r < 16; r++) sh[c][r] = g_agg[(n0 + r) * D + c];
    __syncthreads();

    float bo = b_out[c];
    unsigned long long op[8];
#pragma unroll
    for (int p = 0; p < 8; p++) op[p] = pack2(bo, bo);
#pragma unroll 4
    for (int k = 0; k < D; k++) {
        float w = W_out[k * D + c];
        unsigned long long ww = pack2(w, w);
#pragma unroll
        for (int p = 0; p < 8; p++) {
            unsigned long long ap = *(const unsigned long long*)&sh[k][2 * p];
            op[p] = fma2(ap, ww, op[p]);
        }
    }
#pragma unroll
    for (int p = 0; p < 8; p++) {
        float o0, o1;
        unpack2(op[p], o0, o1);
        out[(n0 + 2 * p) * D + c]     = fmaxf(o0, 0.0f);
        out[(n0 + 2 * p + 1) * D + c] = fmaxf(o1, 0.0f);
    }
}

// ---------------- launch ----------------
extern "C" void kernel_launch(void* const* d_in, const int* in_sizes, int n_in,
                              void* d_out, int out_size) {
    const float* x     = (const float*)d_in[0];
    const float* pos   = (const float*)d_in[1];
    const void*  ei    = d_in[2];
    const float* W_in  = (const float*)d_in[3];
    const float* b_in  = (const float*)d_in[4];
    const float* W_lin = (const float*)d_in[5];
    const float* W_src = (const float*)d_in[6];
    // d_in[7] = W_dst: dead (dst-side softmax terms cancel)
    const float* W_pos = (const float*)d_in[8];
    const float* b_pos = (const float*)d_in[9];
    const float* W_out = (const float*)d_in[10];
    const float* b_out = (const float*)d_in[11];
    float* out = (float*)d_out;

    k_nodehist<<<NPB, 64>>>(ei, x, pos, W_in, b_in, W_lin, W_src, W_pos);
    k_scan_lookback<<<NB, 1024>>>();
    k_scatter<<<(N_EDGES + 255) / 256, 256>>>(ei);
    k_edge<<<(N_NODES + 7) / 8, 256>>>(pos, W_pos, b_pos);
    k_outproj<<<N_NODES / 16, 64>>>(W_out, b_out, out);
}